// round 10
// baseline (speedup 1.0000x reference)
#include <cuda_runtime.h>
#include <math.h>

#define B_ 64
#define T_ 512
#define H_ 256
#define G_ 1024
#define BH_ (B_*H_)

// ---------------- static device scratch (no allocations) ----------------
__device__ float g_x [(size_t)T_*B_*256];   // x,  row m = t*64+b
__device__ float g_gx[(size_t)T_*B_*G_];    // gx, row m = t*64+b
__device__ float g_h [(size_t)(T_+1)*BH_];  // h history [(T+1), B, H]
__device__ float g_c [(size_t)(T_+1)*BH_];  // c history

typedef unsigned long long u64;
typedef unsigned int u32;

// ---------------- f32x2 helpers ----------------
__device__ __forceinline__ u64 fma2(u64 a, u64 b, u64 c){
    u64 d; asm("fma.rn.f32x2 %0, %1, %2, %3;" : "=l"(d) : "l"(a), "l"(b), "l"(c)); return d;
}
__device__ __forceinline__ u64 pack2(float x, float y){
    u64 d; asm("mov.b64 %0, {%1, %2};" : "=l"(d)
               : "r"(__float_as_uint(x)), "r"(__float_as_uint(y))); return d;
}
__device__ __forceinline__ float2 unp2(u64 v){
    u32 lo, hi; asm("mov.b64 {%0, %1}, %2;" : "=r"(lo), "=r"(hi) : "l"(v));
    return make_float2(__uint_as_float(lo), __uint_as_float(hi));
}
__device__ __forceinline__ float sigm(float x){ return 1.0f/(1.0f + __expf(-x)); }

// ---------------- cluster / mbarrier helpers ----------------
#define CARRIVE() asm volatile("barrier.cluster.arrive.aligned;" ::: "memory")
#define CWAIT()   asm volatile("barrier.cluster.wait.aligned;"   ::: "memory")

__device__ __forceinline__ void mbar_init(u32 a, u32 cnt){
    asm volatile("mbarrier.init.shared.b64 [%0], %1;" :: "r"(a), "r"(cnt) : "memory");
}
__device__ __forceinline__ void mbar_arrive(u32 a){
    asm volatile("mbarrier.arrive.shared.b64 _, [%0];" :: "r"(a) : "memory");
}
__device__ __forceinline__ void mbar_arrive_expect(u32 a, u32 tx){
    asm volatile("mbarrier.arrive.expect_tx.shared.b64 _, [%0], %1;"
                 :: "r"(a), "r"(tx) : "memory");
}
__device__ __forceinline__ void mbar_wait(u32 a, u32 par){
    u32 done;
    asm volatile("{\n\t.reg .pred p;\n\t"
        "mbarrier.try_wait.parity.acquire.cluster.shared::cta.b64 p, [%1], %2;\n\t"
        "selp.b32 %0,1,0,p;\n\t}"
        : "=r"(done) : "r"(a), "r"(par) : "memory");
    while(!done){
        asm volatile("{\n\t.reg .pred p;\n\t"
            "mbarrier.try_wait.parity.acquire.cluster.shared::cta.b64 p, [%1], %2, 0x989680;\n\t"
            "selp.b32 %0,1,0,p;\n\t}"
            : "=r"(done) : "r"(a), "r"(par) : "memory");
    }
}
// fire-and-forget remote smem store with tx accounting on the peer's mbarrier
__device__ __forceinline__ void st_async_f32(u32 dst, u32 mbar, int rank, float v){
    u32 rd, rm;
    asm volatile("mapa.shared::cluster.u32 %0, %1, %2;" : "=r"(rd) : "r"(dst),  "r"(rank));
    asm volatile("mapa.shared::cluster.u32 %0, %1, %2;" : "=r"(rm) : "r"(mbar), "r"(rank));
    asm volatile("st.async.shared::cluster.mbarrier::complete_tx::bytes.b32 [%0], %1, [%2];"
                 :: "r"(rd), "r"(__float_as_uint(v)), "r"(rm) : "memory");
}

// ---------------- embedding gather + mean + concat ----------------
__global__ __launch_bounds__(128)
void embed_kernel(const int* __restrict__ node, const int* __restrict__ rel,
                  const float* __restrict__ emb)
{
    int pos  = blockIdx.x*4 + (threadIdx.x >> 5);   // pos = b*T + t
    int lane = threadIdx.x & 31;
    int b = pos >> 9, t = pos & 511;
    const float4* E = (const float4*)emb;
    int n0 = __ldg(&node[pos*2+0]);
    int n1 = __ldg(&node[pos*2+1]);
    int r0 = __ldg(&rel[pos*3+0]);
    int r1 = __ldg(&rel[pos*3+1]);
    int r2 = __ldg(&rel[pos*3+2]);
    float4 e0 = __ldg(&E[(size_t)n0*32 + lane]);
    float4 e1 = __ldg(&E[(size_t)n1*32 + lane]);
    float4 f0 = __ldg(&E[(size_t)r0*32 + lane]);
    float4 f1 = __ldg(&E[(size_t)r1*32 + lane]);
    float4 f2 = __ldg(&E[(size_t)r2*32 + lane]);
    float4 nv = make_float4(0.5f*(e0.x+e1.x), 0.5f*(e0.y+e1.y),
                            0.5f*(e0.z+e1.z), 0.5f*(e0.w+e1.w));
    const float th = (1.0f/3.0f);
    float4 rv = make_float4(th*(f0.x+f1.x+f2.x), th*(f0.y+f1.y+f2.y),
                            th*(f0.z+f1.z+f2.z), th*(f0.w+f1.w+f2.w));
    float4* xr = (float4*)(g_x + ((size_t)t*B_ + b)*256);
    xr[lane]      = nv;
    xr[32 + lane] = rv;
}

// ---------------- SGEMM (NT): C[M,N] = A[M,K] * Bw[N,K]^T (+ bias[N]) ----------------
__global__ __launch_bounds__(256, 2)
void sgemm_nt(const float* __restrict__ A, const float* __restrict__ Bw,
              const float* __restrict__ bias, float* __restrict__ C,
              int M, int N, int K)
{
    __shared__ __align__(16) float As[16][128];
    __shared__ __align__(16) float Bs[16][128];
    int tid = threadIdx.x;
    int m0 = blockIdx.y * 128;
    int n0 = blockIdx.x * 128;
    int tx = tid & 15, ty = tid >> 4;

    int r0_ = tid & 127,        kq0 = (tid >> 7);        // 0..1
    int r1_ = r0_,              kq1 = kq0 + 2;           // 2..3

    u64 acc[8][4];
#pragma unroll
    for(int i=0;i<8;i++)
#pragma unroll
        for(int j=0;j<4;j++) acc[i][j] = 0ull;

    float4 av0, av1, bv0, bv1;
    av0 = __ldg((const float4*)(A  + (size_t)(m0+r0_)*K + kq0*4));
    av1 = __ldg((const float4*)(A  + (size_t)(m0+r1_)*K + kq1*4));
    bv0 = __ldg((const float4*)(Bw + (size_t)(n0+r0_)*K + kq0*4));
    bv1 = __ldg((const float4*)(Bw + (size_t)(n0+r1_)*K + kq1*4));
    As[kq0*4+0][r0_]=av0.x; As[kq0*4+1][r0_]=av0.y; As[kq0*4+2][r0_]=av0.z; As[kq0*4+3][r0_]=av0.w;
    As[kq1*4+0][r1_]=av1.x; As[kq1*4+1][r1_]=av1.y; As[kq1*4+2][r1_]=av1.z; As[kq1*4+3][r1_]=av1.w;
    Bs[kq0*4+0][r0_]=bv0.x; Bs[kq0*4+1][r0_]=bv0.y; Bs[kq0*4+2][r0_]=bv0.z; Bs[kq0*4+3][r0_]=bv0.w;
    Bs[kq1*4+0][r1_]=bv1.x; Bs[kq1*4+1][r1_]=bv1.y; Bs[kq1*4+2][r1_]=bv1.z; Bs[kq1*4+3][r1_]=bv1.w;
    __syncthreads();

    for(int kt=0; kt<K; kt+=16){
        bool more = (kt+16 < K);
        if(more){
            av0 = __ldg((const float4*)(A  + (size_t)(m0+r0_)*K + kt+16 + kq0*4));
            av1 = __ldg((const float4*)(A  + (size_t)(m0+r1_)*K + kt+16 + kq1*4));
            bv0 = __ldg((const float4*)(Bw + (size_t)(n0+r0_)*K + kt+16 + kq0*4));
            bv1 = __ldg((const float4*)(Bw + (size_t)(n0+r1_)*K + kt+16 + kq1*4));
        }
#pragma unroll
        for(int k=0;k<16;k++){
            float4 a0 = *(const float4*)&As[k][ty*8];
            float4 a1 = *(const float4*)&As[k][ty*8+4];
            u64 b0 = *(const u64*)&Bs[k][tx*2];
            u64 b1 = *(const u64*)&Bs[k][tx*2 + 32];
            u64 b2 = *(const u64*)&Bs[k][tx*2 + 64];
            u64 b3 = *(const u64*)&Bs[k][tx*2 + 96];
            float af[8] = {a0.x,a0.y,a0.z,a0.w,a1.x,a1.y,a1.z,a1.w};
#pragma unroll
            for(int i=0;i<8;i++){
                u64 aa = pack2(af[i], af[i]);
                acc[i][0] = fma2(aa, b0, acc[i][0]);
                acc[i][1] = fma2(aa, b1, acc[i][1]);
                acc[i][2] = fma2(aa, b2, acc[i][2]);
                acc[i][3] = fma2(aa, b3, acc[i][3]);
            }
        }
        if(more){
            __syncthreads();
            As[kq0*4+0][r0_]=av0.x; As[kq0*4+1][r0_]=av0.y; As[kq0*4+2][r0_]=av0.z; As[kq0*4+3][r0_]=av0.w;
            As[kq1*4+0][r1_]=av1.x; As[kq1*4+1][r1_]=av1.y; As[kq1*4+2][r1_]=av1.z; As[kq1*4+3][r1_]=av1.w;
            Bs[kq0*4+0][r0_]=bv0.x; Bs[kq0*4+1][r0_]=bv0.y; Bs[kq0*4+2][r0_]=bv0.z; Bs[kq0*4+3][r0_]=bv0.w;
            Bs[kq1*4+0][r1_]=bv1.x; Bs[kq1*4+1][r1_]=bv1.y; Bs[kq1*4+2][r1_]=bv1.z; Bs[kq1*4+3][r1_]=bv1.w;
            __syncthreads();
        }
    }
#pragma unroll
    for(int i=0;i<8;i++){
        float* cp = C + (size_t)(m0 + ty*8 + i)*N + n0;
#pragma unroll
        for(int j=0;j<4;j++){
            float2 v = unp2(acc[i][j]);
            int col = 32*j + 2*tx;
            if(bias){
                v.x += __ldg(&bias[n0 + col    ]);
                v.y += __ldg(&bias[n0 + col + 1]);
            }
            *(float2*)(cp + col) = v;
        }
    }
}

// ---------------- warp-autonomous tree-LSTM scan ----------------
// 16 clusters x 8 CTAs x 512 threads. CTA rank r: units [32r,32r+32).
// Warp w: units {2w, 2w+1} (all 4 batches). Thread (rsel=lane>>3, kidx=lane&7):
// gate rows rsel*256+u0+2w{,+1}, K-chunk kidx*32. Gates reduce intra-warp;
// cells computed by lanes 0..7 of the same warp; pushes via st.async.
// NO CTA-wide barrier in the fast path.
#define RS_ 16
struct SSm {
    float fbuf[RS_][1088];   // ring slot s: h_mem[idx], idx&15==s : [4b][8ch x 34f]
    float sh[2][1088];       // deep-old staging, parity by step
    float s_g[16*32];        // per-warp q strip: [w][rsel*8 + uo*4 + b]
    u64   mbar[RS_];
};

__global__ __launch_bounds__(512, 1) __cluster_dims__(8, 1, 1)
void scan_kernel(const int* __restrict__ father, const float* __restrict__ mask,
                 const float* __restrict__ W_hh, const float* __restrict__ b_hh,
                 float* __restrict__ out)
{
    extern __shared__ __align__(16) char smraw[];
    SSm* S = (SSm*)smraw;

    int tid  = threadIdx.x;
    int lane = tid & 31;
    int w    = tid >> 5;          // warp 0..15
    int rank = blockIdx.x & 7;
    int cid  = blockIdx.x >> 3;
    int u0   = rank * 32;
    int rsel = lane >> 3;         // gate 0..3
    int kidx = lane & 7;          // K-chunk

    u32 mb0 = (u32)__cvta_generic_to_shared(&S->mbar[0]);
    u32 fb0 = (u32)__cvta_generic_to_shared(&S->fbuf[0][0]);

    // W_hh slice: 2 rows (units 2w, 2w+1 of gate rsel) x K-chunk 32 (16 u64 each)
    int grow0 = rsel*256 + u0 + 2*w;
    u64 w2[32];
    {
        const u64* Wp0 = (const u64*)(W_hh + (size_t)grow0*256     + kidx*32);
        const u64* Wp1 = (const u64*)(W_hh + (size_t)(grow0+1)*256 + kidx*32);
#pragma unroll
        for(int i=0;i<16;i++){ w2[i] = __ldg(&Wp0[i]); w2[16+i] = __ldg(&Wp1[i]); }
    }

    // cell constants (lanes 0..7): lane = b*2 + uo
    int cb  = lane >> 1;          // batch 0..3 (valid for lane<8)
    int cuo = lane & 1;           // unit offset
    int gu  = u0 + 2*w + cuo;     // global unit
    int bgc = cid*4 + (cb & 3);
    float bh4[4];
#pragma unroll
    for(int g=0; g<4; g++) bh4[g] = __ldg(&b_hh[g*256 + gu]);

    // gx mapping: lane <-> (uo,g,b):  lane = uo + g*2 + b*8
    int uo_g = lane & 1, g_g = (lane >> 1) & 3, b_g = lane >> 3;
    size_t gx_base = (size_t)(cid*4 + b_g)*G_ + g_g*256 + u0 + 2*w + uo_g;

    // ---- init ----
    if(tid == 0){
        for(int s=0;s<RS_;s++) mbar_init(mb0 + s*8, 1);
    }
    __syncthreads();
    if(tid == 0){
        mbar_arrive(mb0);                               // slot 0 phase 0 done
        for(int s=1;s<RS_;s++) mbar_arrive_expect(mb0 + s*8, 4096u);
    }
    for(int i=tid;i<1088;i+=512) S->fbuf[0][i] = 0.0f;  // h_mem[0] = 0
    __syncthreads();
    CARRIVE(); CWAIT();   // peers armed + zeroed before any st.async flies

    // per-step state (for step t, updated each iter)
    int   idxh[4];  for(int b=0;b<4;b++) idxh[b] = 0;   // t=0: idx = 0 (RING slot 0)
    int   oldf = 0;
    float gx_cur = __ldg(&g_gx[gx_base]);               // t=0
    float hpf[8];
    float c_pf = 0.f, c_last = 0.f;
    float hmx = -1e30f, cmx = -1e30f;
    int   cfl = 1;

    for(int t=0; t<T_; t++){
        // periodic full sync: releases old g_h stores for the deep-old path
        if((t & 7) == 0 && t){ CARRIVE(); CWAIT(); }

        // slow path: stage deep-old h (prefetched last step) + one CTA barrier
        if(oldf){
            if(w < 4 && ((oldf >> w) & 1)){
#pragma unroll
                for(int k=0;k<8;k++){
                    int lin = lane*8 + k;
                    S->sh[t&1][w*272 + (lin>>5)*34 + (lin&31)] = hpf[k];
                }
            }
            __syncthreads();
        }

        // ---- prefetches for step t+1 ----
        int idxn[4]; int oldn = 0;
        if(t+1 < T_){
#pragma unroll
            for(int b=0;b<4;b++){
                int f   = __ldg(&father[(cid*4+b)*T_ + t+1]);
                int idx = min(f, t) + 1;
                idxn[b] = idx;
                if(idx < (t+1) - 13) oldn |= (1<<b);
            }
            if(w < 4 && ((oldn >> w) & 1)){
                const float4* hp4 = (const float4*)(g_h + (size_t)idxn[w]*BH_
                                                    + (size_t)(cid*4+w)*H_ + lane*8);
                float4 a = __ldcg(hp4), b4 = __ldcg(hp4+1);
                hpf[0]=a.x; hpf[1]=a.y; hpf[2]=a.z; hpf[3]=a.w;
                hpf[4]=b4.x; hpf[5]=b4.y; hpf[6]=b4.z; hpf[7]=b4.w;
            }
        }
        float mv = 0.f;
        if(lane < 8){
            mv  = __ldg(&mask[bgc*T_ + t]);
            cfl = (idxh[cb] == t);
            if(!cfl) c_pf = __ldcg(&g_c[(size_t)idxh[cb]*BH_ + bgc*H_ + gu]);
        }
        float gx_nxt = 0.f;
        if(t+1 < T_) gx_nxt = __ldg(&g_gx[gx_base + (size_t)(t+1)*B_*G_]);

        // ---- wait current slot (tx-counted; no convergence) ----
        if(t) mbar_wait(mb0 + (t & (RS_-1))*8, (u32)((t >> 4) & 1));

        // ---- dots: 4 batches, intra-warp reduce ----
#pragma unroll
        for(int b=0;b<4;b++){
            const float* hb = ((oldf >> b) & 1)
                ? (&S->sh[t&1][0] + b*272)
                : (&S->fbuf[idxh[b] & (RS_-1)][0] + b*272);
            const u64* hq = (const u64*)(hb + kidx*34);
            u64 a0=0ull, a1=0ull;
#pragma unroll
            for(int i=0;i<16;i++){
                u64 hh = hq[i];
                a0 = fma2(w2[   i], hh, a0);
                a1 = fma2(w2[16+i], hh, a1);
            }
            float2 r0=unp2(a0), r1=unp2(a1);
            float q0=r0.x+r0.y, q1=r1.x+r1.y;
#pragma unroll
            for(int m=1;m<8;m<<=1){
                q0 += __shfl_xor_sync(0xffffffffu, q0, m);
                q1 += __shfl_xor_sync(0xffffffffu, q1, m);
            }
            if(kidx == 0){
                S->s_g[w*32 + rsel*8 +     b] = q0;
                S->s_g[w*32 + rsel*8 + 4 + b] = q1;
            }
        }
        // re-arm slot (t-2) for its use 14 steps from now (all local warps past wait(t-2))
        if(w == 0 && lane == 0 && t >= 2)
            mbar_arrive_expect(mb0 + ((t-2) & (RS_-1))*8, 4096u);
        __syncwarp();

        // gx routing: full-warp shfl (per-lane src), used by cell lanes
        float gxg[4];
#pragma unroll
        for(int g=0; g<4; g++)
            gxg[g] = __shfl_sync(0xffffffffu, gx_cur, (lane&1) + g*2 + ((lane>>1)&3)*8);

        // ---- LSTM cell (lanes 0..7) ----
        if(lane < 8){
            float gate[4];
#pragma unroll
            for(int g=0; g<4; g++)
                gate[g] = S->s_g[w*32 + g*8 + cuo*4 + cb] + gxg[g] + bh4[g];
            float cprev = cfl ? c_last : c_pf;
            float cv  = sigm(gate[1])*cprev + sigm(gate[0])*tanhf(gate[2]);
            float hv  = sigm(gate[3])*tanhf(cv);
            c_last = cv;
            if(t+1 < T_){
                u32 dst  = fb0 + (u32)(((((t+1)&(RS_-1))*1088) + cb*272 + rank*34 + 2*w + cuo)*4);
                u32 mbsl = mb0 + (u32)(((t+1)&(RS_-1))*8);
#pragma unroll
                for(int r2=0;r2<8;r2++) st_async_f32(dst, mbsl, r2, hv);
            }
            size_t o = (size_t)(t+1)*BH_ + (size_t)bgc*H_ + gu;
            __stcg(&g_h[o], hv);
            __stcg(&g_c[o], cv);
            float hm = hv*mv;
            out[(size_t)bgc*(T_*H_) + (size_t)t*H_ + gu] = hm;
            hmx = fmaxf(hmx, hm);
            cmx = fmaxf(cmx, cv*mv);
        }

        // shift state
        oldf = oldn;
#pragma unroll
        for(int b=0;b<4;b++) idxh[b] = idxn[b];
        gx_cur = gx_nxt;
    }

    if(lane < 8){
        size_t base = (size_t)2*B_*T_*H_;
        out[base +       (size_t)bgc*H_ + gu] = hmx;   // h_max
        out[base + BH_ + (size_t)bgc*H_ + gu] = cmx;   // c_max
    }
}

extern "C" void kernel_launch(void* const* d_in, const int* in_sizes, int n_in,
                              void* d_out, int out_size)
{
    const int*   node   = (const int*)  d_in[0];
    const int*   rel    = (const int*)  d_in[1];
    const int*   father = (const int*)  d_in[2];
    const float* mask   = (const float*)d_in[3];
    const float* emb    = (const float*)d_in[4];
    const float* W_ih   = (const float*)d_in[5];
    const float* W_hh   = (const float*)d_in[6];
    const float* b_ih   = (const float*)d_in[7];
    const float* b_hh   = (const float*)d_in[8];
    const float* W_h    = (const float*)d_in[9];
    float* out = (float*)d_out;

    float *px, *pgx;
    cudaGetSymbolAddress((void**)&px,  g_x);
    cudaGetSymbolAddress((void**)&pgx, g_gx);

    embed_kernel<<<(B_*T_)/4, 128>>>(node, rel, emb);

    dim3 g1(G_/128, (B_*T_)/128);
    sgemm_nt<<<g1, 256>>>(px, W_ih, b_ih, pgx, B_*T_, G_, 256);

    cudaFuncSetAttribute(scan_kernel, cudaFuncAttributeMaxDynamicSharedMemorySize,
                         (int)sizeof(SSm));
    scan_kernel<<<128, 512, sizeof(SSm)>>>(father, mask, W_hh, b_hh, out);

    dim3 g2(H_/128, (B_*T_)/128);
    sgemm_nt<<<g2, 256>>>(out, W_h, (const float*)nullptr,
                          out + (size_t)B_*T_*H_, B_*T_, H_, 256);
}

// round 11
// speedup vs baseline: 1.6055x; 1.6055x over previous
#include <cuda_runtime.h>
#include <math.h>

#define B_ 64
#define T_ 512
#define H_ 256
#define G_ 1024
#define BH_ (B_*H_)
#define BT_ (B_*T_)
#define MPAR_ 18
#define NCTA_ (MPAR_*8)

// ---------------- static device scratch (no allocations) ----------------
__device__ float g_x [(size_t)T_*B_*256];   // x,  row m = t*64+b
__device__ float g_gx[(size_t)T_*B_*G_];    // gx, row m = t*64+b
__device__ float g_h [(size_t)(T_+1)*BH_];  // h history [(T+1), B, H]
__device__ float g_c [(size_t)(T_+1)*BH_];  // c history
// levelization
__device__ int      g_nodes[BT_];           // packed (b<<20)|(t<<10)|fidx, level-major
__device__ int      g_cntB [B_*512];        // [b][lvl]
__device__ int      g_lvl  [BT_];
__device__ int      g_rnk  [BT_];
__device__ int      g_fx   [BT_];
__device__ int      g_off2 [512*B_];        // [lvl][b] start slot
__device__ int      g_lvlOff[513];
__device__ int      g_D[1];
__device__ unsigned g_bar;

typedef unsigned long long u64;
typedef unsigned int u32;

// ---------------- f32x2 helpers ----------------
__device__ __forceinline__ u64 fma2(u64 a, u64 b, u64 c){
    u64 d; asm("fma.rn.f32x2 %0, %1, %2, %3;" : "=l"(d) : "l"(a), "l"(b), "l"(c)); return d;
}
__device__ __forceinline__ u64 pack2(float x, float y){
    u64 d; asm("mov.b64 %0, {%1, %2};" : "=l"(d)
               : "r"(__float_as_uint(x)), "r"(__float_as_uint(y))); return d;
}
__device__ __forceinline__ float2 unp2(u64 v){
    u32 lo, hi; asm("mov.b64 {%0, %1}, %2;" : "=r"(lo), "=r"(hi) : "l"(v));
    return make_float2(__uint_as_float(lo), __uint_as_float(hi));
}
__device__ __forceinline__ float sigm(float x){ return 1.0f/(1.0f + __expf(-x)); }

// ---------------- embedding gather + mean + concat ----------------
__global__ __launch_bounds__(128)
void embed_kernel(const int* __restrict__ node, const int* __restrict__ rel,
                  const float* __restrict__ emb)
{
    int pos  = blockIdx.x*4 + (threadIdx.x >> 5);   // pos = b*T + t
    int lane = threadIdx.x & 31;
    int b = pos >> 9, t = pos & 511;
    const float4* E = (const float4*)emb;
    int n0 = __ldg(&node[pos*2+0]);
    int n1 = __ldg(&node[pos*2+1]);
    int r0 = __ldg(&rel[pos*3+0]);
    int r1 = __ldg(&rel[pos*3+1]);
    int r2 = __ldg(&rel[pos*3+2]);
    float4 e0 = __ldg(&E[(size_t)n0*32 + lane]);
    float4 e1 = __ldg(&E[(size_t)n1*32 + lane]);
    float4 f0 = __ldg(&E[(size_t)r0*32 + lane]);
    float4 f1 = __ldg(&E[(size_t)r1*32 + lane]);
    float4 f2 = __ldg(&E[(size_t)r2*32 + lane]);
    float4 nv = make_float4(0.5f*(e0.x+e1.x), 0.5f*(e0.y+e1.y),
                            0.5f*(e0.z+e1.z), 0.5f*(e0.w+e1.w));
    const float th = (1.0f/3.0f);
    float4 rv = make_float4(th*(f0.x+f1.x+f2.x), th*(f0.y+f1.y+f2.y),
                            th*(f0.z+f1.z+f2.z), th*(f0.w+f1.w+f2.w));
    float4* xr = (float4*)(g_x + ((size_t)t*B_ + b)*256);
    xr[lane]      = nv;
    xr[32 + lane] = rv;
}

// ---------------- SGEMM (NT): C[M,N] = A[M,K] * Bw[N,K]^T (+ bias[N]) ----------------
__global__ __launch_bounds__(256, 2)
void sgemm_nt(const float* __restrict__ A, const float* __restrict__ Bw,
              const float* __restrict__ bias, float* __restrict__ C,
              int M, int N, int K)
{
    __shared__ __align__(16) float As[16][128];
    __shared__ __align__(16) float Bs[16][128];
    int tid = threadIdx.x;
    int m0 = blockIdx.y * 128;
    int n0 = blockIdx.x * 128;
    int tx = tid & 15, ty = tid >> 4;

    int r0_ = tid & 127,        kq0 = (tid >> 7);
    int r1_ = r0_,              kq1 = kq0 + 2;

    u64 acc[8][4];
#pragma unroll
    for(int i=0;i<8;i++)
#pragma unroll
        for(int j=0;j<4;j++) acc[i][j] = 0ull;

    float4 av0, av1, bv0, bv1;
    av0 = __ldg((const float4*)(A  + (size_t)(m0+r0_)*K + kq0*4));
    av1 = __ldg((const float4*)(A  + (size_t)(m0+r1_)*K + kq1*4));
    bv0 = __ldg((const float4*)(Bw + (size_t)(n0+r0_)*K + kq0*4));
    bv1 = __ldg((const float4*)(Bw + (size_t)(n0+r1_)*K + kq1*4));
    As[kq0*4+0][r0_]=av0.x; As[kq0*4+1][r0_]=av0.y; As[kq0*4+2][r0_]=av0.z; As[kq0*4+3][r0_]=av0.w;
    As[kq1*4+0][r1_]=av1.x; As[kq1*4+1][r1_]=av1.y; As[kq1*4+2][r1_]=av1.z; As[kq1*4+3][r1_]=av1.w;
    Bs[kq0*4+0][r0_]=bv0.x; Bs[kq0*4+1][r0_]=bv0.y; Bs[kq0*4+2][r0_]=bv0.z; Bs[kq0*4+3][r0_]=bv0.w;
    Bs[kq1*4+0][r1_]=bv1.x; Bs[kq1*4+1][r1_]=bv1.y; Bs[kq1*4+2][r1_]=bv1.z; Bs[kq1*4+3][r1_]=bv1.w;
    __syncthreads();

    for(int kt=0; kt<K; kt+=16){
        bool more = (kt+16 < K);
        if(more){
            av0 = __ldg((const float4*)(A  + (size_t)(m0+r0_)*K + kt+16 + kq0*4));
            av1 = __ldg((const float4*)(A  + (size_t)(m0+r1_)*K + kt+16 + kq1*4));
            bv0 = __ldg((const float4*)(Bw + (size_t)(n0+r0_)*K + kt+16 + kq0*4));
            bv1 = __ldg((const float4*)(Bw + (size_t)(n0+r1_)*K + kt+16 + kq1*4));
        }
#pragma unroll
        for(int k=0;k<16;k++){
            float4 a0 = *(const float4*)&As[k][ty*8];
            float4 a1 = *(const float4*)&As[k][ty*8+4];
            u64 b0 = *(const u64*)&Bs[k][tx*2];
            u64 b1 = *(const u64*)&Bs[k][tx*2 + 32];
            u64 b2 = *(const u64*)&Bs[k][tx*2 + 64];
            u64 b3 = *(const u64*)&Bs[k][tx*2 + 96];
            float af[8] = {a0.x,a0.y,a0.z,a0.w,a1.x,a1.y,a1.z,a1.w};
#pragma unroll
            for(int i=0;i<8;i++){
                u64 aa = pack2(af[i], af[i]);
                acc[i][0] = fma2(aa, b0, acc[i][0]);
                acc[i][1] = fma2(aa, b1, acc[i][1]);
                acc[i][2] = fma2(aa, b2, acc[i][2]);
                acc[i][3] = fma2(aa, b3, acc[i][3]);
            }
        }
        if(more){
            __syncthreads();
            As[kq0*4+0][r0_]=av0.x; As[kq0*4+1][r0_]=av0.y; As[kq0*4+2][r0_]=av0.z; As[kq0*4+3][r0_]=av0.w;
            As[kq1*4+0][r1_]=av1.x; As[kq1*4+1][r1_]=av1.y; As[kq1*4+2][r1_]=av1.z; As[kq1*4+3][r1_]=av1.w;
            Bs[kq0*4+0][r0_]=bv0.x; Bs[kq0*4+1][r0_]=bv0.y; Bs[kq0*4+2][r0_]=bv0.z; Bs[kq0*4+3][r0_]=bv0.w;
            Bs[kq1*4+0][r1_]=bv1.x; Bs[kq1*4+1][r1_]=bv1.y; Bs[kq1*4+2][r1_]=bv1.z; Bs[kq1*4+3][r1_]=bv1.w;
            __syncthreads();
        }
    }
#pragma unroll
    for(int i=0;i<8;i++){
        float* cp = C + (size_t)(m0 + ty*8 + i)*N + n0;
#pragma unroll
        for(int j=0;j<4;j++){
            float2 v = unp2(acc[i][j]);
            int col = 32*j + 2*tx;
            if(bias){
                v.x += __ldg(&bias[n0 + col    ]);
                v.y += __ldg(&bias[n0 + col + 1]);
            }
            *(float2*)(cp + col) = v;
        }
    }
}

// ---------------- levelizer 1: per-batch depths + ranks (64 CTAs x 512) ----------------
__global__ __launch_bounds__(512)
void lvl1_kernel(const int* __restrict__ father)
{
    __shared__ int anc[2][512], dep[2][512], lvl[512], cnt[512];
    int t = threadIdx.x, b = blockIdx.x;
    int f  = __ldg(&father[b*T_ + t]);
    int fx = min(f, t-1) + 1;                  // in [0, t]
    anc[0][t] = fx - 1;                        // -1 = zero-state parent
    dep[0][t] = (fx > 0) ? 1 : 0;
    cnt[t] = 0;
    __syncthreads();
#pragma unroll
    for(int r=0; r<9; r++){
        int cur = r & 1, nxt = cur ^ 1;
        int a = anc[cur][t], d = dep[cur][t];
        if(a >= 0){ d += dep[cur][a]; a = anc[cur][a]; }
        anc[nxt][t] = a; dep[nxt][t] = d;
        __syncthreads();
    }
    int L = dep[1][t];                         // 9 rounds end in buffer 1
    lvl[t] = L;
    atomicAdd(&cnt[L], 1);
    __syncthreads();
    // rank = # of t' < t with same level (stable order)
    int rk = 0;
    for(int tp=0; tp<t; tp++) rk += (lvl[tp] == L);
    g_lvl[b*T_ + t] = L;
    g_rnk[b*T_ + t] = rk;
    g_fx [b*T_ + t] = fx;
    g_cntB[b*512 + t] = cnt[t];                // t reused as level index
}

// ---------------- levelizer 2: cross-batch offsets (1 CTA x 512) ----------------
__global__ __launch_bounds__(512)
void lvl2_kernel()
{
    __shared__ int tot[512], off[513];
    int l = threadIdx.x;
    int s = 0;
    for(int b=0;b<B_;b++) s += g_cntB[b*512 + l];
    tot[l] = s;
    __syncthreads();
    if(l == 0){
        int run = 0, D = 1;
        for(int i=0;i<512;i++){
            off[i] = run; run += tot[i];
            if(tot[i] > 0) D = i+1;
        }
        off[512] = run;
        g_D[0] = D;
        g_bar  = 0;                            // reset grid barrier (every call)
    }
    __syncthreads();
    g_lvlOff[l] = off[l];
    if(l == 0) g_lvlOff[512] = off[512];
    int run2 = off[l];
    for(int b=0;b<B_;b++){
        g_off2[l*B_ + b] = run2;
        run2 += g_cntB[b*512 + l];
    }
}

// ---------------- levelizer 3: compact node list + zero h0/c0 (64 CTAs x 512) ----------------
__global__ __launch_bounds__(512)
void lvl3_kernel()
{
    int b = blockIdx.x, t = threadIdx.x;
    int idx = b*T_ + t;
    int L  = g_lvl[idx];
    int slot = g_off2[L*B_ + b] + g_rnk[idx];
    g_nodes[slot] = (b << 20) | (t << 10) | g_fx[idx];
    int z = blockIdx.x*512 + threadIdx.x;
    if(z < BH_){ g_h[z] = 0.0f; g_c[z] = 0.0f; }
}

// ---------------- persistent levelized scan ----------------
// 144 CTAs = 18 M-slots x 8 unit-ranks. CTA(rank): units [32r,32r+32) -> 128 gate
// rows, W_hh slice register-resident (thread: 4 rows x 32 K). Per level: gather h
// rows, f32x2 dots, fused cell. Grid barrier between levels.
struct ScanSm {
    float hs[32*272];    // 32 nodes, padded rows (8 chunks x 34 floats)
    float qb[32*128];    // gates per node (lr = gate*32 + u)
    int   nmeta[32];
};

__global__ __launch_bounds__(256, 1)
void scan_kernel(const float* __restrict__ W_hh, const float* __restrict__ b_hh,
                 const float* __restrict__ mask, float* __restrict__ out)
{
    extern __shared__ __align__(16) char smraw[];
    ScanSm* S = (ScanSm*)smraw;

    int tid  = threadIdx.x;
    int rank = blockIdx.x & 7;
    int msl  = blockIdx.x >> 3;
    int u0   = rank * 32;
    int kidx = tid & 7;
    int rg   = tid >> 3;                       // 0..31

    // W_hh slice: 4 gate rows x 32 K-floats (16 u64 each) -> 128 regs
    u64 w2[64];
#pragma unroll
    for(int rj=0; rj<4; rj++){
        int lr   = rg*4 + rj;                  // 0..127
        int grow = (lr>>5)*256 + u0 + (lr&31);
        const u64* Wp = (const u64*)(W_hh + (size_t)grow*256 + kidx*32);
#pragma unroll
        for(int i=0;i<16;i++) w2[rj*16+i] = __ldg(&Wp[i]);
    }

    int D = g_D[0];
    unsigned phase = 0;

    for(int l=0; l<D; l++){
        int o0 = g_lvlOff[l], o1 = g_lvlOff[l+1];
        int ntile = (o1 - o0 + 31) >> 5;

        for(int mt = msl; mt < ntile; mt += MPAR_){
            int base = o0 + mt*32;
            int nn   = min(32, o1 - base);
            __syncthreads();
            if(tid < nn) S->nmeta[tid] = g_nodes[base + tid];
            __syncthreads();

            // stage gathered h rows (write-once-before-read -> plain loads OK)
#pragma unroll 4
            for(int j=0;j<32;j++){
                int lin = j*256 + tid;
                int n = lin >> 6, p = lin & 63;
                if(n < nn){
                    int v  = S->nmeta[n];
                    int fx = v & 1023, b = v >> 20;
                    float4 hv = *((const float4*)(g_h + (size_t)fx*BH_ + b*256) + p);
                    int c = p >> 3, w = (p*4) & 31;
                    float* dst = S->hs + n*272 + c*34 + w;
                    *(float2*)(dst)   = make_float2(hv.x, hv.y);
                    *(float2*)(dst+2) = make_float2(hv.z, hv.w);
                }
            }
            __syncthreads();

            // dots
            for(int n=0; n<nn; n++){
                const u64* hq = (const u64*)(S->hs + n*272 + kidx*34);
                u64 a0=0ull, a1=0ull, a2=0ull, a3=0ull;
#pragma unroll
                for(int i=0;i<16;i++){
                    u64 hh = hq[i];
                    a0 = fma2(w2[     i], hh, a0);
                    a1 = fma2(w2[16 + i], hh, a1);
                    a2 = fma2(w2[32 + i], hh, a2);
                    a3 = fma2(w2[48 + i], hh, a3);
                }
                float2 r0=unp2(a0), r1=unp2(a1), r2=unp2(a2), r3=unp2(a3);
                float q0=r0.x+r0.y, q1=r1.x+r1.y, q2=r2.x+r2.y, q3=r3.x+r3.y;
#pragma unroll
                for(int m=1;m<8;m<<=1){
                    q0 += __shfl_xor_sync(0xffffffffu, q0, m);
                    q1 += __shfl_xor_sync(0xffffffffu, q1, m);
                    q2 += __shfl_xor_sync(0xffffffffu, q2, m);
                    q3 += __shfl_xor_sync(0xffffffffu, q3, m);
                }
                if(kidx == 0){
                    S->qb[n*128 + rg*4 + 0] = q0;
                    S->qb[n*128 + rg*4 + 1] = q1;
                    S->qb[n*128 + rg*4 + 2] = q2;
                    S->qb[n*128 + rg*4 + 3] = q3;
                }
            }
            __syncthreads();

            // fused LSTM cell: 32 nodes x 32 units
#pragma unroll
            for(int e=0;e<4;e++){
                int idx = e*256 + tid;
                int n = idx >> 5, u = idx & 31;
                if(n < nn){
                    int v  = S->nmeta[n];
                    int fx = v & 1023, t = (v >> 10) & 1023, b = v >> 20;
                    size_t gxr = ((size_t)t*B_ + b)*G_;
                    int gu = u0 + u;
                    float gi = S->qb[n*128 +      u] + __ldg(&g_gx[gxr +       gu]) + __ldg(&b_hh[      gu]);
                    float gf = S->qb[n*128 + 32 + u] + __ldg(&g_gx[gxr + 256 + gu]) + __ldg(&b_hh[256 + gu]);
                    float gg = S->qb[n*128 + 64 + u] + __ldg(&g_gx[gxr + 512 + gu]) + __ldg(&b_hh[512 + gu]);
                    float go = S->qb[n*128 + 96 + u] + __ldg(&g_gx[gxr + 768 + gu]) + __ldg(&b_hh[768 + gu]);
                    float cp = g_c[(size_t)fx*BH_ + b*256 + gu];
                    float cv = sigm(gf)*cp + sigm(gi)*tanhf(gg);
                    float hv = sigm(go)*tanhf(cv);
                    size_t o = (size_t)(t+1)*BH_ + b*256 + gu;
                    g_h[o] = hv;
                    g_c[o] = cv;
                    float mv = __ldg(&mask[b*T_ + t]);
                    out[(size_t)b*(T_*H_) + (size_t)t*H_ + gu] = hv*mv;
                }
            }
        }

        // grid barrier between levels
        phase++;
        __threadfence();
        __syncthreads();
        if(tid == 0){
            atomicAdd(&g_bar, 1u);
            unsigned target = phase * NCTA_;
            while(*((volatile unsigned*)&g_bar) < target) __nanosleep(64);
            __threadfence();
        }
        __syncthreads();
    }
}

// ---------------- masked max epilogue ----------------
__global__ __launch_bounds__(256)
void maxes_kernel(const float* __restrict__ mask, float* __restrict__ out)
{
    int idx = blockIdx.x*256 + threadIdx.x;     // 0..BH-1
    int b = idx >> 8, u = idx & 255;
    float hm = -1e30f, cm = -1e30f;
    for(int t=0; t<T_; t++){
        float h  = out[(size_t)b*(T_*H_) + (size_t)t*H_ + u];   // already h*mask
        float mv = __ldg(&mask[b*T_ + t]);
        float c  = g_c[(size_t)(t+1)*BH_ + b*256 + u] * mv;
        hm = fmaxf(hm, h);
        cm = fmaxf(cm, c);
    }
    size_t base = (size_t)2*B_*T_*H_;
    out[base +        idx] = hm;
    out[base + BH_ +  idx] = cm;
}

extern "C" void kernel_launch(void* const* d_in, const int* in_sizes, int n_in,
                              void* d_out, int out_size)
{
    const int*   node   = (const int*)  d_in[0];
    const int*   rel    = (const int*)  d_in[1];
    const int*   father = (const int*)  d_in[2];
    const float* mask   = (const float*)d_in[3];
    const float* emb    = (const float*)d_in[4];
    const float* W_ih   = (const float*)d_in[5];
    const float* W_hh   = (const float*)d_in[6];
    const float* b_ih   = (const float*)d_in[7];
    const float* b_hh   = (const float*)d_in[8];
    const float* W_h    = (const float*)d_in[9];
    float* out = (float*)d_out;

    float *px, *pgx;
    cudaGetSymbolAddress((void**)&px,  g_x);
    cudaGetSymbolAddress((void**)&pgx, g_gx);

    embed_kernel<<<(B_*T_)/4, 128>>>(node, rel, emb);

    dim3 g1(G_/128, (B_*T_)/128);
    sgemm_nt<<<g1, 256>>>(px, W_ih, b_ih, pgx, B_*T_, G_, 256);

    lvl1_kernel<<<B_, 512>>>(father);
    lvl2_kernel<<<1, 512>>>();
    lvl3_kernel<<<B_, 512>>>();

    cudaFuncSetAttribute(scan_kernel, cudaFuncAttributeMaxDynamicSharedMemorySize,
                         (int)sizeof(ScanSm));
    scan_kernel<<<NCTA_, 256, sizeof(ScanSm)>>>(W_hh, b_hh, mask, out);

    maxes_kernel<<<BH_/256, 256>>>(mask, out);

    dim3 g2(H_/128, (B_*T_)/128);
    sgemm_nt<<<g2, 256>>>(out, W_h, (const float*)nullptr,
                          out + (size_t)B_*T_*H_, B_*T_, H_, 256);
}

// round 12
// speedup vs baseline: 1.7587x; 1.0954x over previous
#include <cuda_runtime.h>
#include <math.h>

#define B_ 64
#define T_ 512
#define H_ 256
#define G_ 1024
#define BH_ (B_*H_)
#define BT_ (B_*T_)
#define MPAR_ 18
#define NCTA_ (MPAR_*8)

// ---------------- static device scratch (no allocations) ----------------
__device__ float g_x [(size_t)T_*B_*256];   // x,  row m = t*64+b
__device__ float g_gx[(size_t)T_*B_*G_];    // gx, row m = t*64+b
__device__ float g_h [(size_t)(T_+1)*BH_];  // h history [(T+1), B, H]
__device__ float g_c [(size_t)(T_+1)*BH_];  // c history
// levelization
__device__ int      g_nodes[BT_];           // packed (b<<20)|(t<<10)|fidx, level-major
__device__ int      g_cntB [B_*512];        // [b][lvl]
__device__ int      g_off2 [512*B_];        // [lvl][b] start slot
__device__ int      g_lvlOff[513];
__device__ int      g_D[1];
__device__ unsigned g_bar;                  // scan grid barrier (reset by lvlall)
__device__ unsigned g_cnt2;                 // lvlall sense barrier (self-restoring)
__device__ unsigned g_sns;

typedef unsigned long long u64;
typedef unsigned int u32;

// ---------------- f32x2 helpers ----------------
__device__ __forceinline__ u64 fma2(u64 a, u64 b, u64 c){
    u64 d; asm("fma.rn.f32x2 %0, %1, %2, %3;" : "=l"(d) : "l"(a), "l"(b), "l"(c)); return d;
}
__device__ __forceinline__ u64 pack2(float x, float y){
    u64 d; asm("mov.b64 %0, {%1, %2};" : "=l"(d)
               : "r"(__float_as_uint(x)), "r"(__float_as_uint(y))); return d;
}
__device__ __forceinline__ float2 unp2(u64 v){
    u32 lo, hi; asm("mov.b64 {%0, %1}, %2;" : "=r"(lo), "=r"(hi) : "l"(v));
    return make_float2(__uint_as_float(lo), __uint_as_float(hi));
}
__device__ __forceinline__ float sigm(float x){ return 1.0f/(1.0f + __expf(-x)); }
__device__ __forceinline__ float tanh_f(float x){   // accurate for tiny x, cheap
    float ax = fabsf(x);
    if(ax < 0.25f){
        float x2 = x*x;
        return x*(1.0f + x2*(-0.33333333f + x2*(0.13333333f - x2*0.053968254f)));
    }
    return tanhf(x);
}

// ---------------- embedding gather + mean + concat ----------------
__global__ __launch_bounds__(128)
void embed_kernel(const int* __restrict__ node, const int* __restrict__ rel,
                  const float* __restrict__ emb)
{
    int pos  = blockIdx.x*4 + (threadIdx.x >> 5);   // pos = b*T + t
    int lane = threadIdx.x & 31;
    int b = pos >> 9, t = pos & 511;
    const float4* E = (const float4*)emb;
    int n0 = __ldg(&node[pos*2+0]);
    int n1 = __ldg(&node[pos*2+1]);
    int r0 = __ldg(&rel[pos*3+0]);
    int r1 = __ldg(&rel[pos*3+1]);
    int r2 = __ldg(&rel[pos*3+2]);
    float4 e0 = __ldg(&E[(size_t)n0*32 + lane]);
    float4 e1 = __ldg(&E[(size_t)n1*32 + lane]);
    float4 f0 = __ldg(&E[(size_t)r0*32 + lane]);
    float4 f1 = __ldg(&E[(size_t)r1*32 + lane]);
    float4 f2 = __ldg(&E[(size_t)r2*32 + lane]);
    float4 nv = make_float4(0.5f*(e0.x+e1.x), 0.5f*(e0.y+e1.y),
                            0.5f*(e0.z+e1.z), 0.5f*(e0.w+e1.w));
    const float th = (1.0f/3.0f);
    float4 rv = make_float4(th*(f0.x+f1.x+f2.x), th*(f0.y+f1.y+f2.y),
                            th*(f0.z+f1.z+f2.z), th*(f0.w+f1.w+f2.w));
    float4* xr = (float4*)(g_x + ((size_t)t*B_ + b)*256);
    xr[lane]      = nv;
    xr[32 + lane] = rv;
}

// ---------------- SGEMM (NT): C[M,N] = A[M,K] * Bw[N,K]^T (+ bias[N]) ----------------
__global__ __launch_bounds__(256, 2)
void sgemm_nt(const float* __restrict__ A, const float* __restrict__ Bw,
              const float* __restrict__ bias, float* __restrict__ C,
              int M, int N, int K)
{
    __shared__ __align__(16) float As[16][128];
    __shared__ __align__(16) float Bs[16][128];
    int tid = threadIdx.x;
    int m0 = blockIdx.y * 128;
    int n0 = blockIdx.x * 128;
    int tx = tid & 15, ty = tid >> 4;

    int r0_ = tid & 127,        kq0 = (tid >> 7);
    int r1_ = r0_,              kq1 = kq0 + 2;

    u64 acc[8][4];
#pragma unroll
    for(int i=0;i<8;i++)
#pragma unroll
        for(int j=0;j<4;j++) acc[i][j] = 0ull;

    float4 av0, av1, bv0, bv1;
    av0 = __ldg((const float4*)(A  + (size_t)(m0+r0_)*K + kq0*4));
    av1 = __ldg((const float4*)(A  + (size_t)(m0+r1_)*K + kq1*4));
    bv0 = __ldg((const float4*)(Bw + (size_t)(n0+r0_)*K + kq0*4));
    bv1 = __ldg((const float4*)(Bw + (size_t)(n0+r1_)*K + kq1*4));
    As[kq0*4+0][r0_]=av0.x; As[kq0*4+1][r0_]=av0.y; As[kq0*4+2][r0_]=av0.z; As[kq0*4+3][r0_]=av0.w;
    As[kq1*4+0][r1_]=av1.x; As[kq1*4+1][r1_]=av1.y; As[kq1*4+2][r1_]=av1.z; As[kq1*4+3][r1_]=av1.w;
    Bs[kq0*4+0][r0_]=bv0.x; Bs[kq0*4+1][r0_]=bv0.y; Bs[kq0*4+2][r0_]=bv0.z; Bs[kq0*4+3][r0_]=bv0.w;
    Bs[kq1*4+0][r1_]=bv1.x; Bs[kq1*4+1][r1_]=bv1.y; Bs[kq1*4+2][r1_]=bv1.z; Bs[kq1*4+3][r1_]=bv1.w;
    __syncthreads();

    for(int kt=0; kt<K; kt+=16){
        bool more = (kt+16 < K);
        if(more){
            av0 = __ldg((const float4*)(A  + (size_t)(m0+r0_)*K + kt+16 + kq0*4));
            av1 = __ldg((const float4*)(A  + (size_t)(m0+r1_)*K + kt+16 + kq1*4));
            bv0 = __ldg((const float4*)(Bw + (size_t)(n0+r0_)*K + kt+16 + kq0*4));
            bv1 = __ldg((const float4*)(Bw + (size_t)(n0+r1_)*K + kt+16 + kq1*4));
        }
#pragma unroll
        for(int k=0;k<16;k++){
            float4 a0 = *(const float4*)&As[k][ty*8];
            float4 a1 = *(const float4*)&As[k][ty*8+4];
            u64 b0 = *(const u64*)&Bs[k][tx*2];
            u64 b1 = *(const u64*)&Bs[k][tx*2 + 32];
            u64 b2 = *(const u64*)&Bs[k][tx*2 + 64];
            u64 b3 = *(const u64*)&Bs[k][tx*2 + 96];
            float af[8] = {a0.x,a0.y,a0.z,a0.w,a1.x,a1.y,a1.z,a1.w};
#pragma unroll
            for(int i=0;i<8;i++){
                u64 aa = pack2(af[i], af[i]);
                acc[i][0] = fma2(aa, b0, acc[i][0]);
                acc[i][1] = fma2(aa, b1, acc[i][1]);
                acc[i][2] = fma2(aa, b2, acc[i][2]);
                acc[i][3] = fma2(aa, b3, acc[i][3]);
            }
        }
        if(more){
            __syncthreads();
            As[kq0*4+0][r0_]=av0.x; As[kq0*4+1][r0_]=av0.y; As[kq0*4+2][r0_]=av0.z; As[kq0*4+3][r0_]=av0.w;
            As[kq1*4+0][r1_]=av1.x; As[kq1*4+1][r1_]=av1.y; As[kq1*4+2][r1_]=av1.z; As[kq1*4+3][r1_]=av1.w;
            Bs[kq0*4+0][r0_]=bv0.x; Bs[kq0*4+1][r0_]=bv0.y; Bs[kq0*4+2][r0_]=bv0.z; Bs[kq0*4+3][r0_]=bv0.w;
            Bs[kq1*4+0][r1_]=bv1.x; Bs[kq1*4+1][r1_]=bv1.y; Bs[kq1*4+2][r1_]=bv1.z; Bs[kq1*4+3][r1_]=bv1.w;
            __syncthreads();
        }
    }
#pragma unroll
    for(int i=0;i<8;i++){
        float* cp = C + (size_t)(m0 + ty*8 + i)*N + n0;
#pragma unroll
        for(int j=0;j<4;j++){
            float2 v = unp2(acc[i][j]);
            int col = 32*j + 2*tx;
            if(bias){
                v.x += __ldg(&bias[n0 + col    ]);
                v.y += __ldg(&bias[n0 + col + 1]);
            }
            *(float2*)(cp + col) = v;
        }
    }
}

// ---------------- merged levelizer (64 CTAs x 512, 2 internal grid barriers) ----------
__device__ __forceinline__ void gbar64(unsigned &ls){
    __syncthreads();
    if(threadIdx.x == 0){
        unsigned s = ls ^ 1u;
        __threadfence();
        unsigned a = atomicAdd(&g_cnt2, 1u);
        if(a == 63u){
            atomicExch(&g_cnt2, 0u);
            atomicExch(&g_sns, s);
        } else {
            while(atomicAdd(&g_sns, 0u) != s) __nanosleep(32);
        }
        __threadfence();
        ls = s;
    }
    __syncthreads();
}

__global__ __launch_bounds__(512)
void lvlall_kernel(const int* __restrict__ father)
{
    __shared__ int anc[2][512], dep[2][512], slvl[512], cnt[512];
    int t = threadIdx.x, b = blockIdx.x;
    unsigned ls = 0;

    // phase A: per-batch depth via pointer doubling + stable rank
    int f  = __ldg(&father[b*T_ + t]);
    int fx = min(f, t-1) + 1;                  // in [0, t]
    anc[0][t] = fx - 1;
    dep[0][t] = (fx > 0) ? 1 : 0;
    cnt[t] = 0;
    __syncthreads();
#pragma unroll
    for(int r=0; r<9; r++){
        int cur = r & 1, nxt = cur ^ 1;
        int a = anc[cur][t], d = dep[cur][t];
        if(a >= 0){ d += dep[cur][a]; a = anc[cur][a]; }
        anc[nxt][t] = a; dep[nxt][t] = d;
        __syncthreads();
    }
    int L = dep[1][t];
    slvl[t] = L;
    atomicAdd(&cnt[L], 1);
    __syncthreads();
    int rk = 0;
    for(int tp=0; tp<t; tp++) rk += (slvl[tp] == L);
    g_cntB[b*512 + t] = cnt[t];

    gbar64(ls);

    // phase B: CTA 0 computes offsets (threads parallel over levels)
    if(b == 0){
        __shared__ int off[513];
        int s = 0;
        for(int bb=0; bb<B_; bb++) s += g_cntB[bb*512 + t];
        slvl[t] = s;            // reuse smem as per-level totals
        __syncthreads();
        if(t == 0){
            int run = 0, D = 1;
            for(int i=0;i<512;i++){
                off[i] = run; run += slvl[i];
                if(slvl[i] > 0) D = i+1;
            }
            off[512] = run;
            g_D[0] = D;
            g_bar  = 0;          // reset scan grid barrier (graph-replay safe)
        }
        __syncthreads();
        g_lvlOff[t] = off[t];
        if(t == 0) g_lvlOff[512] = off[512];
        int run2 = off[t];
        for(int bb=0; bb<B_; bb++){
            g_off2[t*B_ + bb] = run2;
            run2 += g_cntB[bb*512 + t];
        }
    }

    gbar64(ls);

    // phase C: compact node list + zero h0/c0
    int slot = g_off2[L*B_ + b] + rk;
    g_nodes[slot] = (b << 20) | (t << 10) | fx;
    int z = b*512 + t;
    if(z < BH_){ g_h[z] = 0.0f; g_c[z] = 0.0f; }
}

// ---------------- persistent levelized scan ----------------
// 144 CTAs = 18 M-slots x 8 unit-ranks. CTA(rank): units [32r,32r+32) -> 128 gate
// rows, W_hh register-resident (thread: 4 rows x 32 K). Per level: reg-staged gather
// pipeline, f32x2 dots, fused cell. Grid barrier between levels.
struct ScanSm {
    float hs[32*272];    // 32 nodes, padded rows (8 chunks x 34 floats)
    float qb[32*128];    // gates per node (lr = gate*32 + u)
};

__global__ __launch_bounds__(256, 1)
void scan_kernel(const float* __restrict__ W_hh, const float* __restrict__ b_hh,
                 const float* __restrict__ mask, float* __restrict__ out)
{
    extern __shared__ __align__(16) char smraw[];
    ScanSm* S = (ScanSm*)smraw;

    int tid  = threadIdx.x;
    int rank = blockIdx.x & 7;
    int msl  = blockIdx.x >> 3;
    int u0   = rank * 32;
    int kidx = tid & 7;
    int rg   = tid >> 3;                       // 0..31
    int cu   = tid & 31;                       // cell unit (fixed per thread)
    int gu   = u0 + cu;

    // W_hh slice: 4 gate rows x 32 K-floats (16 u64 each) -> 128 regs
    u64 w2[64];
#pragma unroll
    for(int rj=0; rj<4; rj++){
        int lr   = rg*4 + rj;
        int grow = (lr>>5)*256 + u0 + (lr&31);
        const u64* Wp = (const u64*)(W_hh + (size_t)grow*256 + kidx*32);
#pragma unroll
        for(int i=0;i<16;i++) w2[rj*16+i] = __ldg(&Wp[i]);
    }
    // hoisted biases for the cell (gu constant per thread)
    float bh4[4];
#pragma unroll
    for(int g=0; g<4; g++) bh4[g] = __ldg(&b_hh[g*256 + gu]);

    int D = g_D[0];
    unsigned phase = 0;

    for(int l=0; l<D; l++){
        int o0 = g_lvlOff[l], o1 = g_lvlOff[l+1];
        int ntile = (o1 - o0 + 31) >> 5;

        float4 sv[8];
        int    svn[8];
        // prologue: prefetch first tile of this CTA's slice
        if(msl < ntile){
            int base = o0 + msl*32;
            int nn   = min(32, o1 - base);
#pragma unroll
            for(int j=0;j<8;j++){
                int lin = j*256 + tid;          // 0..2047
                int n = lin >> 6, p = lin & 63;
                svn[j] = (n < nn) ? 1 : 0;
                if(n < nn){
                    int v  = __ldg(&g_nodes[base + n]);
                    int fx = v & 1023, bb = v >> 20;
                    sv[j] = __ldcg((const float4*)(g_h + (size_t)fx*BH_ + bb*256) + p);
                }
            }
        }

        for(int mt = msl; mt < ntile; mt += MPAR_){
            int base = o0 + mt*32;
            int nn   = min(32, o1 - base);

            // store staged regs -> smem
#pragma unroll
            for(int j=0;j<8;j++){
                if(svn[j]){
                    int lin = j*256 + tid;
                    int n = lin >> 6, p = lin & 63;
                    int c = p >> 3, wofs = (p & 7)*4;
                    float* dst = S->hs + n*272 + c*34 + wofs;
                    *(float2*)(dst)   = make_float2(sv[j].x, sv[j].y);
                    *(float2*)(dst+2) = make_float2(sv[j].z, sv[j].w);
                }
            }
            __syncthreads();

            // prefetch next tile (overlaps dots)
            int mtn = mt + MPAR_;
            if(mtn < ntile){
                int basen = o0 + mtn*32;
                int nnn   = min(32, o1 - basen);
#pragma unroll
                for(int j=0;j<8;j++){
                    int lin = j*256 + tid;
                    int n = lin >> 6, p = lin & 63;
                    svn[j] = (n < nnn) ? 1 : 0;
                    if(n < nnn){
                        int v  = __ldg(&g_nodes[basen + n]);
                        int fx = v & 1023, bb = v >> 20;
                        sv[j] = __ldcg((const float4*)(g_h + (size_t)fx*BH_ + bb*256) + p);
                    }
                }
            }

            // dots
            for(int n=0; n<nn; n++){
                const u64* hq = (const u64*)(S->hs + n*272 + kidx*34);
                u64 a0=0ull, a1=0ull, a2=0ull, a3=0ull;
#pragma unroll
                for(int i=0;i<16;i++){
                    u64 hh = hq[i];
                    a0 = fma2(w2[     i], hh, a0);
                    a1 = fma2(w2[16 + i], hh, a1);
                    a2 = fma2(w2[32 + i], hh, a2);
                    a3 = fma2(w2[48 + i], hh, a3);
                }
                float2 r0=unp2(a0), r1=unp2(a1), r2=unp2(a2), r3=unp2(a3);
                float q0=r0.x+r0.y, q1=r1.x+r1.y, q2=r2.x+r2.y, q3=r3.x+r3.y;
#pragma unroll
                for(int m=1;m<8;m<<=1){
                    q0 += __shfl_xor_sync(0xffffffffu, q0, m);
                    q1 += __shfl_xor_sync(0xffffffffu, q1, m);
                    q2 += __shfl_xor_sync(0xffffffffu, q2, m);
                    q3 += __shfl_xor_sync(0xffffffffu, q3, m);
                }
                if(kidx == 0){
                    S->qb[n*128 + rg*4 + 0] = q0;
                    S->qb[n*128 + rg*4 + 1] = q1;
                    S->qb[n*128 + rg*4 + 2] = q2;
                    S->qb[n*128 + rg*4 + 3] = q3;
                }
            }
            __syncthreads();

            // fused LSTM cell: 32 nodes x 32 units (unit cu fixed per thread)
#pragma unroll
            for(int e=0;e<4;e++){
                int n = e*8 + (tid >> 5);
                if(n < nn){
                    int v  = __ldg(&g_nodes[base + n]);
                    int fx = v & 1023, t = (v >> 10) & 1023, bb = v >> 20;
                    size_t gxr = ((size_t)t*B_ + bb)*G_;
                    float gi = S->qb[n*128 +      cu] + __ldg(&g_gx[gxr +       gu]) + bh4[0];
                    float gf = S->qb[n*128 + 32 + cu] + __ldg(&g_gx[gxr + 256 + gu]) + bh4[1];
                    float gg = S->qb[n*128 + 64 + cu] + __ldg(&g_gx[gxr + 512 + gu]) + bh4[2];
                    float go = S->qb[n*128 + 96 + cu] + __ldg(&g_gx[gxr + 768 + gu]) + bh4[3];
                    float cp = g_c[(size_t)fx*BH_ + bb*256 + gu];
                    float cv = sigm(gf)*cp + sigm(gi)*tanh_f(gg);
                    float hv = sigm(go)*tanh_f(cv);
                    size_t o = (size_t)(t+1)*BH_ + bb*256 + gu;
                    g_h[o] = hv;
                    g_c[o] = cv;
                    float mv = __ldg(&mask[bb*T_ + t]);
                    out[(size_t)bb*(T_*H_) + (size_t)t*H_ + gu] = hv*mv;
                }
            }
        }

        // grid barrier between levels (monotonic; g_bar reset by lvlall each call)
        phase++;
        __threadfence();
        __syncthreads();
        if(tid == 0){
            atomicAdd(&g_bar, 1u);
            unsigned target = phase * NCTA_;
            while(*((volatile unsigned*)&g_bar) < target) __nanosleep(64);
            __threadfence();
        }
        __syncthreads();
    }
}

// ---------------- masked max epilogue ----------------
__global__ __launch_bounds__(256)
void maxes_kernel(const float* __restrict__ mask, float* __restrict__ out)
{
    int idx = blockIdx.x*256 + threadIdx.x;     // 0..BH-1
    int b = idx >> 8, u = idx & 255;
    float hm = -1e30f, cm = -1e30f;
    for(int t=0; t<T_; t++){
        float h  = out[(size_t)b*(T_*H_) + (size_t)t*H_ + u];   // already h*mask
        float mv = __ldg(&mask[b*T_ + t]);
        float c  = g_c[(size_t)(t+1)*BH_ + b*256 + u] * mv;
        hm = fmaxf(hm, h);
        cm = fmaxf(cm, c);
    }
    size_t base = (size_t)2*B_*T_*H_;
    out[base +        idx] = hm;
    out[base + BH_ +  idx] = cm;
}

extern "C" void kernel_launch(void* const* d_in, const int* in_sizes, int n_in,
                              void* d_out, int out_size)
{
    const int*   node   = (const int*)  d_in[0];
    const int*   rel    = (const int*)  d_in[1];
    const int*   father = (const int*)  d_in[2];
    const float* mask   = (const float*)d_in[3];
    const float* emb    = (const float*)d_in[4];
    const float* W_ih   = (const float*)d_in[5];
    const float* W_hh   = (const float*)d_in[6];
    const float* b_ih   = (const float*)d_in[7];
    const float* b_hh   = (const float*)d_in[8];
    const float* W_h    = (const float*)d_in[9];
    float* out = (float*)d_out;

    float *px, *pgx;
    cudaGetSymbolAddress((void**)&px,  g_x);
    cudaGetSymbolAddress((void**)&pgx, g_gx);

    embed_kernel<<<(B_*T_)/4, 128>>>(node, rel, emb);           // launch 1

    dim3 g1(G_/128, (B_*T_)/128);
    sgemm_nt<<<g1, 256>>>(px, W_ih, b_ih, pgx, B_*T_, G_, 256); // launch 2

    lvlall_kernel<<<B_, 512>>>(father);                          // launch 3

    cudaFuncSetAttribute(scan_kernel, cudaFuncAttributeMaxDynamicSharedMemorySize,
                         (int)sizeof(ScanSm));
    scan_kernel<<<NCTA_, 256, sizeof(ScanSm)>>>(W_hh, b_hh, mask, out);  // launch 4 (profiled)

    maxes_kernel<<<BH_/256, 256>>>(mask, out);                   // launch 5

    dim3 g2(H_/128, (B_*T_)/128);
    sgemm_nt<<<g2, 256>>>(out, W_h, (const float*)nullptr,
                          out + (size_t)B_*T_*H_, B_*T_, H_, 256);  // launch 6
}

// round 13
// speedup vs baseline: 1.9798x; 1.1257x over previous
#include <cuda_runtime.h>
#include <math.h>

#define B_ 64
#define T_ 512
#define H_ 256
#define G_ 1024
#define BH_ (B_*H_)
#define BT_ (B_*T_)
#define MPAR_ 18
#define NRNK_ 16
#define NCTA_ (MPAR_*NRNK_)

// ---------------- static device scratch (no allocations) ----------------
__device__ float g_x [(size_t)T_*B_*256];   // x,  row m = t*64+b
__device__ float g_gx[(size_t)T_*B_*G_];    // gx, row m = t*64+b
__device__ float g_h [(size_t)(T_+1)*BH_];  // h history [(T+1), B, H]
__device__ float g_c [(size_t)(T_+1)*BH_];  // c history
// levelization
__device__ int      g_nodes[BT_];           // packed (b<<20)|(t<<10)|fidx, level-major
__device__ int      g_cntB [B_*512];        // [b][lvl]
__device__ int      g_off2 [512*B_];        // [lvl][b] start slot
__device__ int      g_lvlOff[513];
__device__ int      g_D[1];
__device__ unsigned g_bar;                  // scan grid barrier (reset by lvlall)
__device__ unsigned g_cnt2;                 // lvlall sense barrier (self-restoring)
__device__ unsigned g_sns;

typedef unsigned long long u64;
typedef unsigned int u32;

// ---------------- f32x2 helpers ----------------
__device__ __forceinline__ u64 fma2(u64 a, u64 b, u64 c){
    u64 d; asm("fma.rn.f32x2 %0, %1, %2, %3;" : "=l"(d) : "l"(a), "l"(b), "l"(c)); return d;
}
__device__ __forceinline__ u64 pack2(float x, float y){
    u64 d; asm("mov.b64 %0, {%1, %2};" : "=l"(d)
               : "r"(__float_as_uint(x)), "r"(__float_as_uint(y))); return d;
}
__device__ __forceinline__ float2 unp2(u64 v){
    u32 lo, hi; asm("mov.b64 {%0, %1}, %2;" : "=r"(lo), "=r"(hi) : "l"(v));
    return make_float2(__uint_as_float(lo), __uint_as_float(hi));
}
__device__ __forceinline__ float sigm(float x){ return 1.0f/(1.0f + __expf(-x)); }
__device__ __forceinline__ float tanh_f(float x){   // accurate for tiny x, cheap
    float ax = fabsf(x);
    if(ax < 0.25f){
        float x2 = x*x;
        return x*(1.0f + x2*(-0.33333333f + x2*(0.13333333f - x2*0.053968254f)));
    }
    return tanhf(x);
}

// ---------------- cp.async helpers ----------------
__device__ __forceinline__ void cpasync16(u32 dst, const void* src){
    asm volatile("cp.async.ca.shared.global [%0], [%1], 16;" :: "r"(dst), "l"(src));
}
#define CP_COMMIT() asm volatile("cp.async.commit_group;" ::: "memory")
#define CP_WAIT0()  asm volatile("cp.async.wait_group 0;"  ::: "memory")

// ---------------- embedding gather + mean + concat ----------------
__global__ __launch_bounds__(128)
void embed_kernel(const int* __restrict__ node, const int* __restrict__ rel,
                  const float* __restrict__ emb)
{
    int pos  = blockIdx.x*4 + (threadIdx.x >> 5);   // pos = b*T + t
    int lane = threadIdx.x & 31;
    int b = pos >> 9, t = pos & 511;
    const float4* E = (const float4*)emb;
    int n0 = __ldg(&node[pos*2+0]);
    int n1 = __ldg(&node[pos*2+1]);
    int r0 = __ldg(&rel[pos*3+0]);
    int r1 = __ldg(&rel[pos*3+1]);
    int r2 = __ldg(&rel[pos*3+2]);
    float4 e0 = __ldg(&E[(size_t)n0*32 + lane]);
    float4 e1 = __ldg(&E[(size_t)n1*32 + lane]);
    float4 f0 = __ldg(&E[(size_t)r0*32 + lane]);
    float4 f1 = __ldg(&E[(size_t)r1*32 + lane]);
    float4 f2 = __ldg(&E[(size_t)r2*32 + lane]);
    float4 nv = make_float4(0.5f*(e0.x+e1.x), 0.5f*(e0.y+e1.y),
                            0.5f*(e0.z+e1.z), 0.5f*(e0.w+e1.w));
    const float th = (1.0f/3.0f);
    float4 rv = make_float4(th*(f0.x+f1.x+f2.x), th*(f0.y+f1.y+f2.y),
                            th*(f0.z+f1.z+f2.z), th*(f0.w+f1.w+f2.w));
    float4* xr = (float4*)(g_x + ((size_t)t*B_ + b)*256);
    xr[lane]      = nv;
    xr[32 + lane] = rv;
}

// ---------------- SGEMM (NT): C[M,N] = A[M,K] * Bw[N,K]^T (+ bias[N]) ----------------
__global__ __launch_bounds__(256, 2)
void sgemm_nt(const float* __restrict__ A, const float* __restrict__ Bw,
              const float* __restrict__ bias, float* __restrict__ C,
              int M, int N, int K)
{
    __shared__ __align__(16) float As[16][128];
    __shared__ __align__(16) float Bs[16][128];
    int tid = threadIdx.x;
    int m0 = blockIdx.y * 128;
    int n0 = blockIdx.x * 128;
    int tx = tid & 15, ty = tid >> 4;

    int r0_ = tid & 127,        kq0 = (tid >> 7);
    int r1_ = r0_,              kq1 = kq0 + 2;

    u64 acc[8][4];
#pragma unroll
    for(int i=0;i<8;i++)
#pragma unroll
        for(int j=0;j<4;j++) acc[i][j] = 0ull;

    float4 av0, av1, bv0, bv1;
    av0 = __ldg((const float4*)(A  + (size_t)(m0+r0_)*K + kq0*4));
    av1 = __ldg((const float4*)(A  + (size_t)(m0+r1_)*K + kq1*4));
    bv0 = __ldg((const float4*)(Bw + (size_t)(n0+r0_)*K + kq0*4));
    bv1 = __ldg((const float4*)(Bw + (size_t)(n0+r1_)*K + kq1*4));
    As[kq0*4+0][r0_]=av0.x; As[kq0*4+1][r0_]=av0.y; As[kq0*4+2][r0_]=av0.z; As[kq0*4+3][r0_]=av0.w;
    As[kq1*4+0][r1_]=av1.x; As[kq1*4+1][r1_]=av1.y; As[kq1*4+2][r1_]=av1.z; As[kq1*4+3][r1_]=av1.w;
    Bs[kq0*4+0][r0_]=bv0.x; Bs[kq0*4+1][r0_]=bv0.y; Bs[kq0*4+2][r0_]=bv0.z; Bs[kq0*4+3][r0_]=bv0.w;
    Bs[kq1*4+0][r1_]=bv1.x; Bs[kq1*4+1][r1_]=bv1.y; Bs[kq1*4+2][r1_]=bv1.z; Bs[kq1*4+3][r1_]=bv1.w;
    __syncthreads();

    for(int kt=0; kt<K; kt+=16){
        bool more = (kt+16 < K);
        if(more){
            av0 = __ldg((const float4*)(A  + (size_t)(m0+r0_)*K + kt+16 + kq0*4));
            av1 = __ldg((const float4*)(A  + (size_t)(m0+r1_)*K + kt+16 + kq1*4));
            bv0 = __ldg((const float4*)(Bw + (size_t)(n0+r0_)*K + kt+16 + kq0*4));
            bv1 = __ldg((const float4*)(Bw + (size_t)(n0+r1_)*K + kt+16 + kq1*4));
        }
#pragma unroll
        for(int k=0;k<16;k++){
            float4 a0 = *(const float4*)&As[k][ty*8];
            float4 a1 = *(const float4*)&As[k][ty*8+4];
            u64 b0 = *(const u64*)&Bs[k][tx*2];
            u64 b1 = *(const u64*)&Bs[k][tx*2 + 32];
            u64 b2 = *(const u64*)&Bs[k][tx*2 + 64];
            u64 b3 = *(const u64*)&Bs[k][tx*2 + 96];
            float af[8] = {a0.x,a0.y,a0.z,a0.w,a1.x,a1.y,a1.z,a1.w};
#pragma unroll
            for(int i=0;i<8;i++){
                u64 aa = pack2(af[i], af[i]);
                acc[i][0] = fma2(aa, b0, acc[i][0]);
                acc[i][1] = fma2(aa, b1, acc[i][1]);
                acc[i][2] = fma2(aa, b2, acc[i][2]);
                acc[i][3] = fma2(aa, b3, acc[i][3]);
            }
        }
        if(more){
            __syncthreads();
            As[kq0*4+0][r0_]=av0.x; As[kq0*4+1][r0_]=av0.y; As[kq0*4+2][r0_]=av0.z; As[kq0*4+3][r0_]=av0.w;
            As[kq1*4+0][r1_]=av1.x; As[kq1*4+1][r1_]=av1.y; As[kq1*4+2][r1_]=av1.z; As[kq1*4+3][r1_]=av1.w;
            Bs[kq0*4+0][r0_]=bv0.x; Bs[kq0*4+1][r0_]=bv0.y; Bs[kq0*4+2][r0_]=bv0.z; Bs[kq0*4+3][r0_]=bv0.w;
            Bs[kq1*4+0][r1_]=bv1.x; Bs[kq1*4+1][r1_]=bv1.y; Bs[kq1*4+2][r1_]=bv1.z; Bs[kq1*4+3][r1_]=bv1.w;
            __syncthreads();
        }
    }
#pragma unroll
    for(int i=0;i<8;i++){
        float* cp = C + (size_t)(m0 + ty*8 + i)*N + n0;
#pragma unroll
        for(int j=0;j<4;j++){
            float2 v = unp2(acc[i][j]);
            int col = 32*j + 2*tx;
            if(bias){
                v.x += __ldg(&bias[n0 + col    ]);
                v.y += __ldg(&bias[n0 + col + 1]);
            }
            *(float2*)(cp + col) = v;
        }
    }
}

// ---------------- merged levelizer (64 CTAs x 512, 2 internal grid barriers) ----------
__device__ __forceinline__ void gbar64(unsigned &ls){
    __syncthreads();
    if(threadIdx.x == 0){
        unsigned s = ls ^ 1u;
        __threadfence();
        unsigned a = atomicAdd(&g_cnt2, 1u);
        if(a == 63u){
            atomicExch(&g_cnt2, 0u);
            atomicExch(&g_sns, s);
        } else {
            while(atomicAdd(&g_sns, 0u) != s) __nanosleep(32);
        }
        __threadfence();
        ls = s;
    }
    __syncthreads();
}

__global__ __launch_bounds__(512)
void lvlall_kernel(const int* __restrict__ father)
{
    __shared__ int anc[2][512], dep[2][512], slvl[512], cnt[512];
    int t = threadIdx.x, b = blockIdx.x;
    unsigned ls = 0;

    int f  = __ldg(&father[b*T_ + t]);
    int fx = min(f, t-1) + 1;                  // in [0, t]
    anc[0][t] = fx - 1;
    dep[0][t] = (fx > 0) ? 1 : 0;
    cnt[t] = 0;
    __syncthreads();
#pragma unroll
    for(int r=0; r<9; r++){
        int cur = r & 1, nxt = cur ^ 1;
        int a = anc[cur][t], d = dep[cur][t];
        if(a >= 0){ d += dep[cur][a]; a = anc[cur][a]; }
        anc[nxt][t] = a; dep[nxt][t] = d;
        __syncthreads();
    }
    int L = dep[1][t];
    slvl[t] = L;
    atomicAdd(&cnt[L], 1);
    __syncthreads();
    int rk = 0;
    for(int tp=0; tp<t; tp++) rk += (slvl[tp] == L);
    g_cntB[b*512 + t] = cnt[t];

    gbar64(ls);

    if(b == 0){
        __shared__ int off[513];
        int s = 0;
        for(int bb=0; bb<B_; bb++) s += g_cntB[bb*512 + t];
        slvl[t] = s;
        __syncthreads();
        if(t == 0){
            int run = 0, D = 1;
            for(int i=0;i<512;i++){
                off[i] = run; run += slvl[i];
                if(slvl[i] > 0) D = i+1;
            }
            off[512] = run;
            g_D[0] = D;
            g_bar  = 0;
        }
        __syncthreads();
        g_lvlOff[t] = off[t];
        if(t == 0) g_lvlOff[512] = off[512];
        int run2 = off[t];
        for(int bb=0; bb<B_; bb++){
            g_off2[t*B_ + bb] = run2;
            run2 += g_cntB[bb*512 + t];
        }
    }

    gbar64(ls);

    int slot = g_off2[L*B_ + b] + rk;
    g_nodes[slot] = (b << 20) | (t << 10) | fx;
    int z = b*512 + t;
    if(z < BH_){ g_h[z] = 0.0f; g_c[z] = 0.0f; }
}

// ---------------- persistent levelized scan (v2: 16 ranks, 2 CTAs/SM) ----------------
// 288 CTAs = 18 M-slots x 16 unit-ranks. CTA(rank): units [16r,16r+16) -> 64 gate
// rows; thread: 2 rows x 32 K of W_hh (64 regs). cp.async double-buffered h gather,
// gx/c/mask prefetched to regs. Grid barrier between levels.
struct ScanSm {
    float hs[2][32*288];  // double-buffered gather: 32 nodes x (8 chunks x 36 floats)
    float qb[32*64];      // gates per node (lr = gate*16 + unit)
};

__global__ __launch_bounds__(256, 2)
void scan_kernel(const float* __restrict__ W_hh, const float* __restrict__ b_hh,
                 const float* __restrict__ mask, float* __restrict__ out)
{
    extern __shared__ __align__(16) char smraw[];
    ScanSm* S = (ScanSm*)smraw;
    u32 hs_s = (u32)__cvta_generic_to_shared(&S->hs[0][0]);

    int tid  = threadIdx.x;
    int rank = blockIdx.x & 15;
    int msl  = blockIdx.x >> 4;
    int u0   = rank * 16;
    int kidx = tid & 7;
    int rg   = tid >> 3;                       // 0..31
    int cu   = tid & 15;                       // cell unit
    int gu   = u0 + cu;
    int cn0  = tid >> 4;                       // cell node base 0..15

    // W_hh slice: 2 gate rows x 32 K-floats (16 u64 each) -> 64 regs
    u64 w2[32];
#pragma unroll
    for(int rj=0; rj<2; rj++){
        int lr   = rg*2 + rj;                  // 0..63
        int grow = (lr>>4)*256 + u0 + (lr&15);
        const u64* Wp = (const u64*)(W_hh + (size_t)grow*256 + kidx*32);
#pragma unroll
        for(int i=0;i<16;i++) w2[rj*16+i] = __ldg(&Wp[i]);
    }
    float bh4[4];
#pragma unroll
    for(int g=0; g<4; g++) bh4[g] = __ldg(&b_hh[g*256 + gu]);

    int D = g_D[0];
    unsigned phase = 0;

    for(int l=0; l<D; l++){
        int o0 = g_lvlOff[l], o1 = g_lvlOff[l+1];
        int ntile = (o1 - o0 + 31) >> 5;

        // prologue: async-stage first tile into buf 0
        int buf = 0;
        if(msl < ntile){
            int base = o0 + msl*32;
            int nn   = min(32, o1 - base);
#pragma unroll
            for(int j=0;j<8;j++){
                int lin = j*256 + tid;
                int n = lin >> 6, p = lin & 63;
                if(n < nn){
                    int v  = __ldg(&g_nodes[base + n]);
                    int fx = v & 1023, bb = v >> 20;
                    const float4* src = (const float4*)(g_h + (size_t)fx*BH_ + bb*256) + p;
                    cpasync16(hs_s + (u32)((n*288 + (p>>3)*36 + (p&7)*4)*4), src);
                }
            }
        }
        CP_COMMIT();

        for(int mt = msl; mt < ntile; mt += MPAR_){
            int base = o0 + mt*32;
            int nn   = min(32, o1 - base);

            // prefetch cell operands into regs (independent of dots)
            float gxp[2][4], cpp[2], mvp[2];
            int   tt[2], tb[2];
#pragma unroll
            for(int e=0;e<2;e++){
                int n = e*16 + cn0;
                if(n < nn){
                    int v  = __ldg(&g_nodes[base + n]);
                    int fx = v & 1023; tt[e] = (v >> 10) & 1023; tb[e] = v >> 20;
                    size_t gxr = ((size_t)tt[e]*B_ + tb[e])*G_;
#pragma unroll
                    for(int g=0; g<4; g++) gxp[e][g] = __ldg(&g_gx[gxr + g*256 + gu]);
                    cpp[e] = __ldg(&g_c[(size_t)fx*BH_ + tb[e]*256 + gu]);
                    mvp[e] = __ldg(&mask[tb[e]*T_ + tt[e]]);
                }
            }

            CP_WAIT0();
            __syncthreads();          // staged tile visible to all

            // async-stage next tile into the other buffer (overlaps dots)
            int mtn = mt + MPAR_;
            if(mtn < ntile){
                int basen = o0 + mtn*32;
                int nnn   = min(32, o1 - basen);
                u32 dstb  = hs_s + (u32)((buf^1)*32*288*4);
#pragma unroll
                for(int j=0;j<8;j++){
                    int lin = j*256 + tid;
                    int n = lin >> 6, p = lin & 63;
                    if(n < nnn){
                        int v  = __ldg(&g_nodes[basen + n]);
                        int fx = v & 1023, bb = v >> 20;
                        const float4* src = (const float4*)(g_h + (size_t)fx*BH_ + bb*256) + p;
                        cpasync16(dstb + (u32)((n*288 + (p>>3)*36 + (p&7)*4)*4), src);
                    }
                }
            }
            CP_COMMIT();

            // dots from hs[buf]
            const float* hsb = &S->hs[buf][0];
#pragma unroll 2
            for(int n=0; n<nn; n++){
                const u64* hq = (const u64*)(hsb + n*288 + kidx*36);
                u64 a0=0ull, a1=0ull;
#pragma unroll
                for(int i=0;i<16;i++){
                    u64 hh = hq[i];
                    a0 = fma2(w2[   i], hh, a0);
                    a1 = fma2(w2[16+i], hh, a1);
                }
                float2 r0=unp2(a0), r1=unp2(a1);
                float q0=r0.x+r0.y, q1=r1.x+r1.y;
#pragma unroll
                for(int m=1;m<8;m<<=1){
                    q0 += __shfl_xor_sync(0xffffffffu, q0, m);
                    q1 += __shfl_xor_sync(0xffffffffu, q1, m);
                }
                if(kidx == 0){
                    S->qb[n*64 + rg*2 + 0] = q0;
                    S->qb[n*64 + rg*2 + 1] = q1;
                }
            }
            __syncthreads();

            // fused LSTM cell: 32 nodes x 16 units -> 2 per thread
#pragma unroll
            for(int e=0;e<2;e++){
                int n = e*16 + cn0;
                if(n < nn){
                    float gi = S->qb[n*64 +      cu] + gxp[e][0] + bh4[0];
                    float gf = S->qb[n*64 + 16 + cu] + gxp[e][1] + bh4[1];
                    float gg = S->qb[n*64 + 32 + cu] + gxp[e][2] + bh4[2];
                    float go = S->qb[n*64 + 48 + cu] + gxp[e][3] + bh4[3];
                    float cv = sigm(gf)*cpp[e] + sigm(gi)*tanh_f(gg);
                    float hv = sigm(go)*tanh_f(cv);
                    size_t o = (size_t)(tt[e]+1)*BH_ + tb[e]*256 + gu;
                    g_h[o] = hv;
                    g_c[o] = cv;
                    out[(size_t)tb[e]*(T_*H_) + (size_t)tt[e]*H_ + gu] = hv*mvp[e];
                }
            }
            buf ^= 1;
        }

        // grid barrier between levels (monotonic; g_bar reset by lvlall each call)
        phase++;
        __threadfence();
        __syncthreads();
        if(tid == 0){
            atomicAdd(&g_bar, 1u);
            unsigned target = phase * NCTA_;
            while(*((volatile unsigned*)&g_bar) < target) __nanosleep(64);
            __threadfence();
        }
        __syncthreads();
    }
}

// ---------------- masked max epilogue ----------------
__global__ __launch_bounds__(256)
void maxes_kernel(const float* __restrict__ mask, float* __restrict__ out)
{
    int idx = blockIdx.x*256 + threadIdx.x;     // 0..BH-1
    int b = idx >> 8, u = idx & 255;
    float hm = -1e30f, cm = -1e30f;
    for(int t=0; t<T_; t++){
        float h  = out[(size_t)b*(T_*H_) + (size_t)t*H_ + u];
        float mv = __ldg(&mask[b*T_ + t]);
        float c  = g_c[(size_t)(t+1)*BH_ + b*256 + u] * mv;
        hm = fmaxf(hm, h);
        cm = fmaxf(cm, c);
    }
    size_t base = (size_t)2*B_*T_*H_;
    out[base +        idx] = hm;
    out[base + BH_ +  idx] = cm;
}

extern "C" void kernel_launch(void* const* d_in, const int* in_sizes, int n_in,
                              void* d_out, int out_size)
{
    const int*   node   = (const int*)  d_in[0];
    const int*   rel    = (const int*)  d_in[1];
    const int*   father = (const int*)  d_in[2];
    const float* mask   = (const float*)d_in[3];
    const float* emb    = (const float*)d_in[4];
    const float* W_ih   = (const float*)d_in[5];
    const float* W_hh   = (const float*)d_in[6];
    const float* b_ih   = (const float*)d_in[7];
    const float* b_hh   = (const float*)d_in[8];
    const float* W_h    = (const float*)d_in[9];
    float* out = (float*)d_out;

    float *px, *pgx;
    cudaGetSymbolAddress((void**)&px,  g_x);
    cudaGetSymbolAddress((void**)&pgx, g_gx);

    embed_kernel<<<(B_*T_)/4, 128>>>(node, rel, emb);           // launch 1

    dim3 g1(G_/128, (B_*T_)/128);
    sgemm_nt<<<g1, 256>>>(px, W_ih, b_ih, pgx, B_*T_, G_, 256); // launch 2

    lvlall_kernel<<<B_, 512>>>(father);                          // launch 3

    cudaFuncSetAttribute(scan_kernel, cudaFuncAttributeMaxDynamicSharedMemorySize,
                         (int)sizeof(ScanSm));
    scan_kernel<<<NCTA_, 256, sizeof(ScanSm)>>>(W_hh, b_hh, mask, out);  // launch 4 (profiled)

    maxes_kernel<<<BH_/256, 256>>>(mask, out);                   // launch 5

    dim3 g2(H_/128, (B_*T_)/128);
    sgemm_nt<<<g2, 256>>>(out, W_h, (const float*)nullptr,
                          out + (size_t)B_*T_*H_, B_*T_, H_, 256);  // launch 6
}